// round 6
// baseline (speedup 1.0000x reference)
#include <cuda_runtime.h>
#include <math.h>
#include <stdint.h>

#define NT   16384
#define DDIM 1024
#define NE   64
#define CAP  640

// ---------------- scratch (device globals; no allocation) ----------------
__device__ int   g_topk[NT * 2];
__device__ float g_gates[NT * 2];
__device__ int   g_etok[NE * CAP];
__device__ int   g_ecnt[NE];

// ---------------- packed f32x2 helpers (router) ----------------
__device__ __forceinline__ unsigned long long pack2(float lo, float hi) {
    unsigned long long d;
    asm("mov.b64 %0, {%1, %2};" : "=l"(d) : "f"(lo), "f"(hi));
    return d;
}
__device__ __forceinline__ void unpack2(unsigned long long v, float& lo, float& hi) {
    asm("mov.b64 {%0, %1}, %2;" : "=f"(lo), "=f"(hi) : "l"(v));
}
__device__ __forceinline__ unsigned long long fma2(unsigned long long a,
                                                   unsigned long long b,
                                                   unsigned long long c) {
    unsigned long long d;
    asm("fma.rn.f32x2 %0, %1, %2, %3;" : "=l"(d) : "l"(a), "l"(b), "l"(c));
    return d;
}

// ---------------- mma.sync helpers ----------------
__device__ __forceinline__ uint32_t smem_u32(const void* p) {
    uint32_t a;
    asm("{ .reg .u64 t; cvta.to.shared.u64 t, %1; cvt.u32.u64 %0, t; }" : "=r"(a) : "l"(p));
    return a;
}
__device__ __forceinline__ void ldsm4(uint32_t* r, uint32_t addr) {
    asm volatile("ldmatrix.sync.aligned.m8n8.x4.shared.b16 {%0,%1,%2,%3}, [%4];"
                 : "=r"(r[0]), "=r"(r[1]), "=r"(r[2]), "=r"(r[3]) : "r"(addr));
}
__device__ __forceinline__ void ldsm4t(uint32_t* r, uint32_t addr) {
    asm volatile("ldmatrix.sync.aligned.m8n8.x4.trans.shared.b16 {%0,%1,%2,%3}, [%4];"
                 : "=r"(r[0]), "=r"(r[1]), "=r"(r[2]), "=r"(r[3]) : "r"(addr));
}
__device__ __forceinline__ void mma16816(float* d, const uint32_t* a, const uint32_t* b) {
    asm volatile(
        "mma.sync.aligned.m16n8k16.row.col.f32.bf16.bf16.f32 "
        "{%0,%1,%2,%3}, {%4,%5,%6,%7}, {%8,%9}, {%0,%1,%2,%3};"
        : "+f"(d[0]), "+f"(d[1]), "+f"(d[2]), "+f"(d[3])
        : "r"(a[0]), "r"(a[1]), "r"(a[2]), "r"(a[3]), "r"(b[0]), "r"(b[1]));
}
__device__ __forceinline__ uint32_t pk_bf(float a, float b) {
    uint32_t r;
    asm("cvt.rn.bf16x2.f32 %0, %1, %2;" : "=r"(r) : "f"(b), "f"(a));
    return r;
}

// ---------------- 0) zero output ----------------
__global__ __launch_bounds__(256) void zero_out_kernel(float* __restrict__ out) {
    size_t i = ((size_t)blockIdx.x * 256 + threadIdx.x) * 4;
    *(float4*)(out + i) = make_float4(0.f, 0.f, 0.f, 0.f);
}

// ---------------- 1) router: exact fp32, 128x64 tile, 8x4 per thread ----------------
__global__ __launch_bounds__(256) void router_kernel(const float* __restrict__ x,
                                                     const float* __restrict__ Wr,
                                                     const float* __restrict__ br) {
    __shared__ union {
        struct { float As[32][130]; float Bs[32][68]; } s;
        float Lg[128][65];
    } u;

    int tid = threadIdx.x;
    int m0  = blockIdx.x * 128;
    int tr  = (tid >> 4) * 8;
    int tc  = (tid & 15) * 4;

    unsigned long long acc[4][4];
#pragma unroll
    for (int i = 0; i < 4; i++)
#pragma unroll
        for (int j = 0; j < 4; j++) acc[i][j] = 0ull;

    for (int k0 = 0; k0 < DDIM; k0 += 32) {
#pragma unroll
        for (int i = 0; i < 16; i++) {
            int idx = tid + i * 256;
            int kk = idx & 31, r = idx >> 5;
            u.s.As[kk][r] = x[(size_t)(m0 + r) * DDIM + k0 + kk];
        }
#pragma unroll
        for (int i = 0; i < 8; i++) {
            int idx = tid + i * 256;
            int c = idx & 63, kk = idx >> 6;
            u.s.Bs[kk][c] = Wr[(size_t)(k0 + kk) * NE + c];
        }
        __syncthreads();
#pragma unroll
        for (int kk = 0; kk < 32; kk++) {
            float4 b = *(const float4*)&u.s.Bs[kk][tc];
            unsigned long long bb[4];
            bb[0] = pack2(b.x, b.x);
            bb[1] = pack2(b.y, b.y);
            bb[2] = pack2(b.z, b.z);
            bb[3] = pack2(b.w, b.w);
#pragma unroll
            for (int pr = 0; pr < 4; pr++) {
                unsigned long long a2 = *(const unsigned long long*)&u.s.As[kk][tr + 2 * pr];
#pragma unroll
                for (int c = 0; c < 4; c++) acc[pr][c] = fma2(a2, bb[c], acc[pr][c]);
            }
        }
        __syncthreads();
    }
    float b0 = br[tc], b1 = br[tc + 1], b2 = br[tc + 2], b3 = br[tc + 3];
#pragma unroll
    for (int pr = 0; pr < 4; pr++) {
        float l0, h0, l1, h1, l2, h2, l3, h3;
        unpack2(acc[pr][0], l0, h0);
        unpack2(acc[pr][1], l1, h1);
        unpack2(acc[pr][2], l2, h2);
        unpack2(acc[pr][3], l3, h3);
        int r = tr + 2 * pr;
        u.Lg[r][tc] = l0 + b0;     u.Lg[r][tc + 1] = l1 + b1;
        u.Lg[r][tc + 2] = l2 + b2; u.Lg[r][tc + 3] = l3 + b3;
        u.Lg[r + 1][tc] = h0 + b0;     u.Lg[r + 1][tc + 1] = h1 + b1;
        u.Lg[r + 1][tc + 2] = h2 + b2; u.Lg[r + 1][tc + 3] = h3 + b3;
    }
    __syncthreads();
    if (tid < 128) {
        float m1 = -INFINITY, m2 = -INFINITY;
        int i1 = 0, i2 = 0;
#pragma unroll
        for (int e = 0; e < NE; e++) {
            float v = u.Lg[tid][e];
            if (v > m1) { m2 = m1; i2 = i1; m1 = v; i1 = e; }
            else if (v > m2) { m2 = v; i2 = e; }
        }
        float d = expf(m2 - m1);
        float s = 1.0f / (1.0f + d);
        int n = m0 + tid;
        g_topk[2 * n]      = i1;
        g_topk[2 * n + 1]  = i2;
        g_gates[2 * n]     = s;
        g_gates[2 * n + 1] = d * s;
    }
}

// ---------------- 2) rank ----------------
__global__ __launch_bounds__(256) void rank_kernel() {
    int e   = blockIdx.x;
    int tid = threadIdx.x;
    int lane = tid & 31, w = tid >> 5;

    for (int c = tid; c < CAP; c += 256) g_etok[e * CAP + c] = -1;

    __shared__ int warp_tot[8];
    __shared__ int s_running;
    if (tid == 0) s_running = 0;
    __syncthreads();

    for (int base = 0; base < 2 * NT; base += 256) {
        int p = base + tid;
        int j = p >> 14;
        int n = p & (NT - 1);
        int idx = g_topk[2 * n + j];
        bool m = (idx == e);
        unsigned bal = __ballot_sync(0xffffffffu, m);
        if (lane == 0) warp_tot[w] = __popc(bal);
        int wprefix = __popc(bal & ((1u << lane) - 1u));
        __syncthreads();
        int prev = s_running;
        int wpre = 0;
#pragma unroll
        for (int i = 0; i < 8; i++) if (i < w) wpre += warp_tot[i];
        if (m) {
            int rank = prev + wpre + wprefix;
            if (rank < CAP) g_etok[e * CAP + rank] = (n << 1) | j;
        }
        __syncthreads();
        if (tid == 0) {
            int tot = 0;
#pragma unroll
            for (int i = 0; i < 8; i++) tot += warp_tot[i];
            s_running = prev + tot;
        }
        __syncthreads();
    }
    if (tid == 0) g_ecnt[e] = s_running;
}

// ---------------- 3) expert GEMM: bf16 3-pass, BM128 BN64 BK32, 2 CTA/SM ----------------
#define BK       32
#define NCHUNK   (DDIM / BK)        // 32
#define SA_STR   80                 // 64B data + 16B pad  (20 banks: conflict-free)
#define SB_STR   144                // 128B data + 16B pad (4 mod 32: conflict-free)
#define A_BUF    (128 * SA_STR)     // 10240
#define B_BUF    (32 * SB_STR)      // 4608
#define OFF_ALO  A_BUF
#define OFF_BHI  (2 * A_BUF)
#define OFF_BLO  (2 * A_BUF + B_BUF)
#define STAGE    (2 * A_BUF + 2 * B_BUF)   // 29696
#define GEMM_SMEM (2 * STAGE)              // 59392

__global__ __launch_bounds__(256, 2) void expert_gemm_mma(const float* __restrict__ x,
                                                          const float* __restrict__ We,
                                                          float* __restrict__ out) {
    extern __shared__ char smem[];
    __shared__ int s_tok[128];

    const int e  = blockIdx.z;
    const int m0 = blockIdx.y * 128;
    const int n0 = blockIdx.x * 64;

    if (m0 >= g_ecnt[e]) return;

    const uint32_t sbase = smem_u32(smem);
    const int tid  = threadIdx.x;
    const int lane = tid & 31;
    const int w    = tid >> 5;

    if (tid < 128) s_tok[tid] = g_etok[e * CAP + m0 + tid];
    __syncthreads();

    const int wm = (w >> 1) * 32;   // 4 m-warps
    const int wn = (w & 1) * 32;    // 2 n-warps

    const float* Bb = We + (size_t)e * DDIM * DDIM + n0;

    float acc[2][4][4];
#pragma unroll
    for (int i = 0; i < 2; i++)
#pragma unroll
        for (int j = 0; j < 4; j++)
#pragma unroll
            for (int q = 0; q < 4; q++) acc[i][j][q] = 0.f;

    float4 fa[4], fb[2];

// A: 128x32 = 1024 float4, 4/thread; B: 32x64 = 512 float4, 2/thread
#define LOAD_GLOBAL(K0) do {                                                     \
    _Pragma("unroll")                                                            \
    for (int t = 0; t < 4; t++) {                                                \
        int idx = tid + t * 256; int row = idx >> 3, c4 = idx & 7;               \
        int pk = s_tok[row];                                                     \
        fa[t] = (pk >= 0)                                                        \
            ? *(const float4*)(x + (size_t)(pk >> 1) * DDIM + (K0) + 4 * c4)     \
            : make_float4(0.f, 0.f, 0.f, 0.f);                                   \
    }                                                                            \
    _Pragma("unroll")                                                            \
    for (int t = 0; t < 2; t++) {                                                \
        int idx = tid + t * 256; int kk = idx >> 4, c4 = idx & 15;               \
        fb[t] = *(const float4*)(Bb + (size_t)((K0) + kk) * DDIM + 4 * c4);      \
    }                                                                            \
} while (0)

#define STORE_STAGE(ST) do {                                                     \
    char* sp = smem + (ST) * STAGE;                                              \
    _Pragma("unroll")                                                            \
    for (int t = 0; t < 4; t++) {                                                \
        int idx = tid + t * 256; int row = idx >> 3, c4 = idx & 7;               \
        uint32_t h01 = pk_bf(fa[t].x, fa[t].y);                                  \
        uint32_t h23 = pk_bf(fa[t].z, fa[t].w);                                  \
        float r0 = fa[t].x - __uint_as_float(h01 << 16);                         \
        float r1 = fa[t].y - __uint_as_float(h01 & 0xffff0000u);                 \
        float r2 = fa[t].z - __uint_as_float(h23 << 16);                         \
        float r3 = fa[t].w - __uint_as_float(h23 & 0xffff0000u);                 \
        uint32_t l01 = pk_bf(r0, r1), l23 = pk_bf(r2, r3);                       \
        *(uint2*)(sp + row * SA_STR + c4 * 8) = make_uint2(h01, h23);            \
        *(uint2*)(sp + OFF_ALO + row * SA_STR + c4 * 8) = make_uint2(l01, l23);  \
    }                                                                            \
    _Pragma("unroll")                                                            \
    for (int t = 0; t < 2; t++) {                                                \
        int idx = tid + t * 256; int kk = idx >> 4, c4 = idx & 15;               \
        uint32_t h01 = pk_bf(fb[t].x, fb[t].y);                                  \
        uint32_t h23 = pk_bf(fb[t].z, fb[t].w);                                  \
        float r0 = fb[t].x - __uint_as_float(h01 << 16);                         \
        float r1 = fb[t].y - __uint_as_float(h01 & 0xffff0000u);                 \
        float r2 = fb[t].z - __uint_as_float(h23 << 16);                         \
        float r3 = fb[t].w - __uint_as_float(h23 & 0xffff0000u);                 \
        uint32_t l01 = pk_bf(r0, r1), l23 = pk_bf(r2, r3);                       \
        *(uint2*)(sp + OFF_BHI + kk * SB_STR + c4 * 8) = make_uint2(h01, h23);   \
        *(uint2*)(sp + OFF_BLO + kk * SB_STR + c4 * 8) = make_uint2(l01, l23);   \
    }                                                                            \
} while (0)

#define MMA_KS(KS) do {                                                          \
    uint32_t ah[2][4], al[2][4], bh[2][4], bl[2][4];                             \
    _Pragma("unroll")                                                            \
    for (int mt = 0; mt < 2; mt++) {                                             \
        ldsm4(ah[mt], sb + aoff[mt] + (KS) * 32);                                \
        ldsm4(al[mt], sb + OFF_ALO + aoff[mt] + (KS) * 32);                      \
    }                                                                            \
    _Pragma("unroll")                                                            \
    for (int nt = 0; nt < 2; nt++) {                                             \
        ldsm4t(bh[nt], sb + OFF_BHI + boff[nt] + (KS) * 16 * SB_STR);            \
        ldsm4t(bl[nt], sb + OFF_BLO + boff[nt] + (KS) * 16 * SB_STR);            \
    }                                                                            \
    _Pragma("unroll")                                                            \
    for (int mt = 0; mt < 2; mt++)                                               \
        _Pragma("unroll")                                                        \
        for (int nt8 = 0; nt8 < 4; nt8++) {                                      \
            const int p = nt8 >> 1, q = (nt8 & 1) * 2;                           \
            mma16816(acc[mt][nt8], ah[mt], &bh[p][q]);                           \
            mma16816(acc[mt][nt8], ah[mt], &bl[p][q]);                           \
            mma16816(acc[mt][nt8], al[mt], &bh[p][q]);                           \
        }                                                                        \
} while (0)

    const int la = lane & 15, lhi = lane >> 4;
    uint32_t aoff[2], boff[2];
#pragma unroll
    for (int mt = 0; mt < 2; mt++)
        aoff[mt] = (uint32_t)((wm + mt * 16 + la) * SA_STR + lhi * 16);
#pragma unroll
    for (int nt = 0; nt < 2; nt++)
        boff[nt] = (uint32_t)(la * SB_STR + (wn + nt * 16 + lhi * 8) * 2);

    LOAD_GLOBAL(0);
    STORE_STAGE(0);
    __syncthreads();
    LOAD_GLOBAL(BK);

    for (int ch = 0; ch < NCHUNK; ch++) {
        const int cur = ch & 1;
        const uint32_t sb = sbase + cur * STAGE;
        MMA_KS(0);
        if (ch + 1 < NCHUNK) STORE_STAGE(cur ^ 1);
        MMA_KS(1);
        __syncthreads();
        if (ch + 2 < NCHUNK) LOAD_GLOBAL((ch + 2) * BK);
    }

    // epilogue: gate * relu -> atomic add into out
    const int r0 = lane >> 2, c0 = (lane & 3) * 2;
#pragma unroll
    for (int mt = 0; mt < 2; mt++) {
        int row1 = wm + mt * 16 + r0;
        int p1 = s_tok[row1];
        int p2 = s_tok[row1 + 8];
        if (p1 >= 0) {
            float g = g_gates[p1];
            float* d1 = out + (size_t)(p1 >> 1) * DDIM + n0 + wn + c0;
#pragma unroll
            for (int nt8 = 0; nt8 < 4; nt8++) {
                atomicAdd(d1 + nt8 * 8,     g * fmaxf(acc[mt][nt8][0], 0.f));
                atomicAdd(d1 + nt8 * 8 + 1, g * fmaxf(acc[mt][nt8][1], 0.f));
            }
        }
        if (p2 >= 0) {
            float g = g_gates[p2];
            float* d2 = out + (size_t)(p2 >> 1) * DDIM + n0 + wn + c0;
#pragma unroll
            for (int nt8 = 0; nt8 < 4; nt8++) {
                atomicAdd(d2 + nt8 * 8,     g * fmaxf(acc[mt][nt8][2], 0.f));
                atomicAdd(d2 + nt8 * 8 + 1, g * fmaxf(acc[mt][nt8][3], 0.f));
            }
        }
    }
#undef LOAD_GLOBAL
#undef STORE_STAGE
#undef MMA_KS
}

// ---------------- launch ----------------
extern "C" void kernel_launch(void* const* d_in, const int* in_sizes, int n_in,
                              void* d_out, int out_size) {
    const float* x  = (const float*)d_in[0];
    const float* Wr = (const float*)d_in[1];
    const float* br = (const float*)d_in[2];
    const float* We = (const float*)d_in[3];
    float* out = (float*)d_out;

    cudaFuncSetAttribute(expert_gemm_mma, cudaFuncAttributeMaxDynamicSharedMemorySize, GEMM_SMEM);

    zero_out_kernel<<<NT * DDIM / 1024, 256>>>(out);
    router_kernel<<<NT / 128, 256>>>(x, Wr, br);
    rank_kernel<<<NE, 256>>>();
    expert_gemm_mma<<<dim3(DDIM / 64, CAP / 128, NE), 256, GEMM_SMEM>>>(x, We, out);
}

// round 7
// speedup vs baseline: 1.1170x; 1.1170x over previous
#include <cuda_runtime.h>
#include <math.h>
#include <stdint.h>

#define NT   16384
#define DDIM 1024
#define NE   64
#define CAP  640

// ---------------- scratch (device globals; no allocation) ----------------
__device__ int   g_topk[NT * 2];
__device__ float g_gates[NT * 2];
__device__ int   g_etok[NE * CAP];
__device__ int   g_ecnt[NE];

// ---------------- packed f32x2 helpers (router) ----------------
__device__ __forceinline__ unsigned long long pack2(float lo, float hi) {
    unsigned long long d;
    asm("mov.b64 %0, {%1, %2};" : "=l"(d) : "f"(lo), "f"(hi));
    return d;
}
__device__ __forceinline__ void unpack2(unsigned long long v, float& lo, float& hi) {
    asm("mov.b64 {%0, %1}, %2;" : "=f"(lo), "=f"(hi) : "l"(v));
}
__device__ __forceinline__ unsigned long long fma2(unsigned long long a,
                                                   unsigned long long b,
                                                   unsigned long long c) {
    unsigned long long d;
    asm("fma.rn.f32x2 %0, %1, %2, %3;" : "=l"(d) : "l"(a), "l"(b), "l"(c));
    return d;
}

// ---------------- mma.sync helpers ----------------
__device__ __forceinline__ uint32_t smem_u32(const void* p) {
    uint32_t a;
    asm("{ .reg .u64 t; cvta.to.shared.u64 t, %1; cvt.u32.u64 %0, t; }" : "=r"(a) : "l"(p));
    return a;
}
__device__ __forceinline__ void ldsm4(uint32_t* r, uint32_t addr) {
    asm volatile("ldmatrix.sync.aligned.m8n8.x4.shared.b16 {%0,%1,%2,%3}, [%4];"
                 : "=r"(r[0]), "=r"(r[1]), "=r"(r[2]), "=r"(r[3]) : "r"(addr));
}
__device__ __forceinline__ void ldsm4t(uint32_t* r, uint32_t addr) {
    asm volatile("ldmatrix.sync.aligned.m8n8.x4.trans.shared.b16 {%0,%1,%2,%3}, [%4];"
                 : "=r"(r[0]), "=r"(r[1]), "=r"(r[2]), "=r"(r[3]) : "r"(addr));
}
__device__ __forceinline__ void mma16816(float* d, const uint32_t* a, const uint32_t* b) {
    asm volatile(
        "mma.sync.aligned.m16n8k16.row.col.f32.bf16.bf16.f32 "
        "{%0,%1,%2,%3}, {%4,%5,%6,%7}, {%8,%9}, {%0,%1,%2,%3};"
        : "+f"(d[0]), "+f"(d[1]), "+f"(d[2]), "+f"(d[3])
        : "r"(a[0]), "r"(a[1]), "r"(a[2]), "r"(a[3]), "r"(b[0]), "r"(b[1]));
}
__device__ __forceinline__ uint32_t pk_bf(float a, float b) {
    uint32_t r;
    asm("cvt.rn.bf16x2.f32 %0, %1, %2;" : "=r"(r) : "f"(b), "f"(a));
    return r;
}

// ---------------- 0) zero output ----------------
__global__ __launch_bounds__(256) void zero_out_kernel(float* __restrict__ out) {
    size_t i = ((size_t)blockIdx.x * 256 + threadIdx.x) * 4;
    *(float4*)(out + i) = make_float4(0.f, 0.f, 0.f, 0.f);
}

// ---------------- 1) router: exact fp32, 128x64 tile, 8x4 per thread ----------------
__global__ __launch_bounds__(256) void router_kernel(const float* __restrict__ x,
                                                     const float* __restrict__ Wr,
                                                     const float* __restrict__ br) {
    __shared__ union {
        struct { float As[32][130]; float Bs[32][68]; } s;
        float Lg[128][65];
    } u;

    int tid = threadIdx.x;
    int m0  = blockIdx.x * 128;
    int tr  = (tid >> 4) * 8;
    int tc  = (tid & 15) * 4;

    unsigned long long acc[4][4];
#pragma unroll
    for (int i = 0; i < 4; i++)
#pragma unroll
        for (int j = 0; j < 4; j++) acc[i][j] = 0ull;

    for (int k0 = 0; k0 < DDIM; k0 += 32) {
#pragma unroll
        for (int i = 0; i < 16; i++) {
            int idx = tid + i * 256;
            int kk = idx & 31, r = idx >> 5;
            u.s.As[kk][r] = x[(size_t)(m0 + r) * DDIM + k0 + kk];
        }
#pragma unroll
        for (int i = 0; i < 8; i++) {
            int idx = tid + i * 256;
            int c = idx & 63, kk = idx >> 6;
            u.s.Bs[kk][c] = Wr[(size_t)(k0 + kk) * NE + c];
        }
        __syncthreads();
#pragma unroll
        for (int kk = 0; kk < 32; kk++) {
            float4 b = *(const float4*)&u.s.Bs[kk][tc];
            unsigned long long bb[4];
            bb[0] = pack2(b.x, b.x);
            bb[1] = pack2(b.y, b.y);
            bb[2] = pack2(b.z, b.z);
            bb[3] = pack2(b.w, b.w);
#pragma unroll
            for (int pr = 0; pr < 4; pr++) {
                unsigned long long a2 = *(const unsigned long long*)&u.s.As[kk][tr + 2 * pr];
#pragma unroll
                for (int c = 0; c < 4; c++) acc[pr][c] = fma2(a2, bb[c], acc[pr][c]);
            }
        }
        __syncthreads();
    }
    float b0 = br[tc], b1 = br[tc + 1], b2 = br[tc + 2], b3 = br[tc + 3];
#pragma unroll
    for (int pr = 0; pr < 4; pr++) {
        float l0, h0, l1, h1, l2, h2, l3, h3;
        unpack2(acc[pr][0], l0, h0);
        unpack2(acc[pr][1], l1, h1);
        unpack2(acc[pr][2], l2, h2);
        unpack2(acc[pr][3], l3, h3);
        int r = tr + 2 * pr;
        u.Lg[r][tc] = l0 + b0;     u.Lg[r][tc + 1] = l1 + b1;
        u.Lg[r][tc + 2] = l2 + b2; u.Lg[r][tc + 3] = l3 + b3;
        u.Lg[r + 1][tc] = h0 + b0;     u.Lg[r + 1][tc + 1] = h1 + b1;
        u.Lg[r + 1][tc + 2] = h2 + b2; u.Lg[r + 1][tc + 3] = h3 + b3;
    }
    __syncthreads();
    if (tid < 128) {
        float m1 = -INFINITY, m2 = -INFINITY;
        int i1 = 0, i2 = 0;
#pragma unroll
        for (int e = 0; e < NE; e++) {
            float v = u.Lg[tid][e];
            if (v > m1) { m2 = m1; i2 = i1; m1 = v; i1 = e; }
            else if (v > m2) { m2 = v; i2 = e; }
        }
        float d = expf(m2 - m1);
        float s = 1.0f / (1.0f + d);
        int n = m0 + tid;
        g_topk[2 * n]      = i1;
        g_topk[2 * n + 1]  = i2;
        g_gates[2 * n]     = s;
        g_gates[2 * n + 1] = d * s;
    }
}

// ---------------- 2) rank ----------------
__global__ __launch_bounds__(256) void rank_kernel() {
    int e   = blockIdx.x;
    int tid = threadIdx.x;
    int lane = tid & 31, w = tid >> 5;

    for (int c = tid; c < CAP; c += 256) g_etok[e * CAP + c] = -1;

    __shared__ int warp_tot[8];
    __shared__ int s_running;
    if (tid == 0) s_running = 0;
    __syncthreads();

    for (int base = 0; base < 2 * NT; base += 256) {
        int p = base + tid;
        int j = p >> 14;
        int n = p & (NT - 1);
        int idx = g_topk[2 * n + j];
        bool m = (idx == e);
        unsigned bal = __ballot_sync(0xffffffffu, m);
        if (lane == 0) warp_tot[w] = __popc(bal);
        int wprefix = __popc(bal & ((1u << lane) - 1u));
        __syncthreads();
        int prev = s_running;
        int wpre = 0;
#pragma unroll
        for (int i = 0; i < 8; i++) if (i < w) wpre += warp_tot[i];
        if (m) {
            int rank = prev + wpre + wprefix;
            if (rank < CAP) g_etok[e * CAP + rank] = (n << 1) | j;
        }
        __syncthreads();
        if (tid == 0) {
            int tot = 0;
#pragma unroll
            for (int i = 0; i < 8; i++) tot += warp_tot[i];
            s_running = prev + tot;
        }
        __syncthreads();
    }
    if (tid == 0) g_ecnt[e] = s_running;
}

// ---------------- 3) expert GEMM: bf16 3-pass, BM128 BN128 BK64, staggered stores ----------------
#define BK       64
#define NCHUNK   (DDIM / BK)        // 16
#define SA_STR   144
#define SB_STR   272
#define A_BUF    (128 * SA_STR)
#define B_BUF    (64 * SB_STR)
#define OFF_ALO  A_BUF
#define OFF_BHI  (2 * A_BUF)
#define OFF_BLO  (2 * A_BUF + B_BUF)
#define STAGE    (2 * A_BUF + 2 * B_BUF)
#define GEMM_SMEM (2 * STAGE)

__global__ __launch_bounds__(256, 1) void expert_gemm_mma(const float* __restrict__ x,
                                                          const float* __restrict__ We,
                                                          float* __restrict__ out) {
    extern __shared__ char smem[];
    __shared__ int s_tok[128];

    const int e  = blockIdx.z;
    const int m0 = blockIdx.y * 128;
    const int n0 = blockIdx.x * 128;

    if (m0 >= g_ecnt[e]) return;

    const uint32_t sbase = smem_u32(smem);
    const int tid  = threadIdx.x;
    const int lane = tid & 31;
    const int w    = tid >> 5;
    const int wslot = w >> 1;          // 0..3: which ks step this warp stores after

    if (tid < 128) s_tok[tid] = g_etok[e * CAP + m0 + tid];
    __syncthreads();

    const int wm = (w >> 2) * 64;
    const int wn = (w & 3) * 32;

    const float* Bb = We + (size_t)e * DDIM * DDIM + n0;

    float acc[4][4][4];
#pragma unroll
    for (int i = 0; i < 4; i++)
#pragma unroll
        for (int j = 0; j < 4; j++)
#pragma unroll
            for (int q = 0; q < 4; q++) acc[i][j][q] = 0.f;

    float4 fa[8], fb[8];

#define LOAD_GLOBAL(K0) do {                                                     \
    _Pragma("unroll")                                                            \
    for (int t = 0; t < 8; t++) {                                                \
        int idx = tid + t * 256; int row = idx >> 4, c4 = idx & 15;              \
        int pk = s_tok[row];                                                     \
        fa[t] = (pk >= 0)                                                        \
            ? *(const float4*)(x + (size_t)(pk >> 1) * DDIM + (K0) + 4 * c4)     \
            : make_float4(0.f, 0.f, 0.f, 0.f);                                   \
    }                                                                            \
    _Pragma("unroll")                                                            \
    for (int t = 0; t < 8; t++) {                                                \
        int idx = tid + t * 256; int kk = idx >> 5, c4 = idx & 31;               \
        fb[t] = *(const float4*)(Bb + (size_t)((K0) + kk) * DDIM + 4 * c4);      \
    }                                                                            \
} while (0)

#define STORE_STAGE(ST) do {                                                     \
    char* sp = smem + (ST) * STAGE;                                              \
    _Pragma("unroll")                                                            \
    for (int t = 0; t < 8; t++) {                                                \
        int idx = tid + t * 256; int row = idx >> 4, c4 = idx & 15;              \
        uint32_t h01 = pk_bf(fa[t].x, fa[t].y);                                  \
        uint32_t h23 = pk_bf(fa[t].z, fa[t].w);                                  \
        float r0 = fa[t].x - __uint_as_float(h01 << 16);                         \
        float r1 = fa[t].y - __uint_as_float(h01 & 0xffff0000u);                 \
        float r2 = fa[t].z - __uint_as_float(h23 << 16);                         \
        float r3 = fa[t].w - __uint_as_float(h23 & 0xffff0000u);                 \
        uint32_t l01 = pk_bf(r0, r1), l23 = pk_bf(r2, r3);                       \
        *(uint2*)(sp + row * SA_STR + c4 * 8) = make_uint2(h01, h23);            \
        *(uint2*)(sp + OFF_ALO + row * SA_STR + c4 * 8) = make_uint2(l01, l23);  \
    }                                                                            \
    _Pragma("unroll")                                                            \
    for (int t = 0; t < 8; t++) {                                                \
        int idx = tid + t * 256; int kk = idx >> 5, c4 = idx & 31;               \
        uint32_t h01 = pk_bf(fb[t].x, fb[t].y);                                  \
        uint32_t h23 = pk_bf(fb[t].z, fb[t].w);                                  \
        float r0 = fb[t].x - __uint_as_float(h01 << 16);                         \
        float r1 = fb[t].y - __uint_as_float(h01 & 0xffff0000u);                 \
        float r2 = fb[t].z - __uint_as_float(h23 << 16);                         \
        float r3 = fb[t].w - __uint_as_float(h23 & 0xffff0000u);                 \
        uint32_t l01 = pk_bf(r0, r1), l23 = pk_bf(r2, r3);                       \
        *(uint2*)(sp + OFF_BHI + kk * SB_STR + c4 * 8) = make_uint2(h01, h23);   \
        *(uint2*)(sp + OFF_BLO + kk * SB_STR + c4 * 8) = make_uint2(l01, l23);   \
    }                                                                            \
} while (0)

#define MMA_KS(KS) do {                                                          \
    uint32_t ah[4][4], al[4][4], bh[2][4], bl[2][4];                             \
    _Pragma("unroll")                                                            \
    for (int mt = 0; mt < 4; mt++) {                                             \
        ldsm4(ah[mt], sb + aoff[mt] + (KS) * 32);                                \
        ldsm4(al[mt], sb + OFF_ALO + aoff[mt] + (KS) * 32);                      \
    }                                                                            \
    _Pragma("unroll")                                                            \
    for (int nt = 0; nt < 2; nt++) {                                             \
        ldsm4t(bh[nt], sb + OFF_BHI + boff[nt] + (KS) * 16 * SB_STR);            \
        ldsm4t(bl[nt], sb + OFF_BLO + boff[nt] + (KS) * 16 * SB_STR);            \
    }                                                                            \
    _Pragma("unroll")                                                            \
    for (int mt = 0; mt < 4; mt++)                                               \
        _Pragma("unroll")                                                        \
        for (int nt8 = 0; nt8 < 4; nt8++) {                                      \
            const int p = nt8 >> 1, q = (nt8 & 1) * 2;                           \
            mma16816(acc[mt][nt8], ah[mt], &bh[p][q]);                           \
            mma16816(acc[mt][nt8], ah[mt], &bl[p][q]);                           \
            mma16816(acc[mt][nt8], al[mt], &bh[p][q]);                           \
        }                                                                        \
} while (0)

    const int la = lane & 15, lhi = lane >> 4;
    uint32_t aoff[4], boff[2];
#pragma unroll
    for (int mt = 0; mt < 4; mt++)
        aoff[mt] = (uint32_t)((wm + mt * 16 + la) * SA_STR + lhi * 16);
#pragma unroll
    for (int nt = 0; nt < 2; nt++)
        boff[nt] = (uint32_t)(la * SB_STR + (wn + nt * 16 + lhi * 8) * 2);

    // prologue
    LOAD_GLOBAL(0);
    STORE_STAGE(0);
    __syncthreads();
    LOAD_GLOBAL(BK);

    for (int ch = 0; ch < NCHUNK; ch++) {
        const int cur = ch & 1;
        const uint32_t sb = sbase + cur * STAGE;
        // warp-staggered store+prefetch: each warp-pair services its slot after
        // its designated ks step, so >=6 warps keep the tensor pipe fed.
        MMA_KS(0);
        if (wslot == 0 && ch + 1 < NCHUNK) {
            STORE_STAGE(cur ^ 1);
            if (ch + 2 < NCHUNK) LOAD_GLOBAL((ch + 2) * BK);
        }
        MMA_KS(1);
        if (wslot == 1 && ch + 1 < NCHUNK) {
            STORE_STAGE(cur ^ 1);
            if (ch + 2 < NCHUNK) LOAD_GLOBAL((ch + 2) * BK);
        }
        MMA_KS(2);
        if (wslot == 2 && ch + 1 < NCHUNK) {
            STORE_STAGE(cur ^ 1);
            if (ch + 2 < NCHUNK) LOAD_GLOBAL((ch + 2) * BK);
        }
        MMA_KS(3);
        if (wslot == 3 && ch + 1 < NCHUNK) {
            STORE_STAGE(cur ^ 1);
            if (ch + 2 < NCHUNK) LOAD_GLOBAL((ch + 2) * BK);
        }
        __syncthreads();
    }

    // epilogue: gate * relu -> atomic add into out (<=2 commutative adds/elem: deterministic)
    const int r0 = lane >> 2, c0 = (lane & 3) * 2;
#pragma unroll
    for (int mt = 0; mt < 4; mt++) {
        int row1 = wm + mt * 16 + r0;
        int p1 = s_tok[row1];
        int p2 = s_tok[row1 + 8];
        if (p1 >= 0) {
            float g = g_gates[p1];
            float* d1 = out + (size_t)(p1 >> 1) * DDIM + n0 + wn + c0;
#pragma unroll
            for (int nt8 = 0; nt8 < 4; nt8++) {
                atomicAdd(d1 + nt8 * 8,     g * fmaxf(acc[mt][nt8][0], 0.f));
                atomicAdd(d1 + nt8 * 8 + 1, g * fmaxf(acc[mt][nt8][1], 0.f));
            }
        }
        if (p2 >= 0) {
            float g = g_gates[p2];
            float* d2 = out + (size_t)(p2 >> 1) * DDIM + n0 + wn + c0;
#pragma unroll
            for (int nt8 = 0; nt8 < 4; nt8++) {
                atomicAdd(d2 + nt8 * 8,     g * fmaxf(acc[mt][nt8][2], 0.f));
                atomicAdd(d2 + nt8 * 8 + 1, g * fmaxf(acc[mt][nt8][3], 0.f));
            }
        }
    }
#undef LOAD_GLOBAL
#undef STORE_STAGE
#undef MMA_KS
}

// ---------------- launch ----------------
extern "C" void kernel_launch(void* const* d_in, const int* in_sizes, int n_in,
                              void* d_out, int out_size) {
    const float* x  = (const float*)d_in[0];
    const float* Wr = (const float*)d_in[1];
    const float* br = (const float*)d_in[2];
    const float* We = (const float*)d_in[3];
    float* out = (float*)d_out;

    cudaFuncSetAttribute(expert_gemm_mma, cudaFuncAttributeMaxDynamicSharedMemorySize, GEMM_SMEM);

    zero_out_kernel<<<NT * DDIM / 1024, 256>>>(out);
    router_kernel<<<NT / 128, 256>>>(x, Wr, br);
    rank_kernel<<<NE, 256>>>();
    expert_gemm_mma<<<dim3(DDIM / 128, CAP / 128, NE), 256, GEMM_SMEM>>>(x, We, out);
}